// round 16
// baseline (speedup 1.0000x reference)
#include <cuda_runtime.h>
#include <math.h>

// Problem constants
#define Nn 8
#define Cc 8
#define Tt 600
#define Ff 257
#define NCHUNK 30
#define TCHUNK 20               // Tt / NCHUNK
#define LOADC 7.0710678118654754e-04f   // 0.001/sqrt(2)
#define TFv (Tt * Ff)           // 154200
#define HTF (TFv / 2)           // 77100  (t and t+300 share f)
#define GCOV (NCHUNK * Ff)      // 7710 dense (chunk,f) work items per n

// Scratch (device globals — no allocation allowed)
__device__ __align__(16) float g_phi[(size_t)NCHUNK * Nn * 72 * Ff];
__device__ __align__(16) float g_phired[(size_t)Nn * 72 * Ff];
__device__ __align__(16) float g_w16[(size_t)Nn * Ff * 16];   // [n][f][2c(+1)] interleaved conj(w)

// ---- packed f32x2 helpers (Blackwell FFMA2) --------------------------------
__device__ __forceinline__ unsigned long long pk2(float lo, float hi) {
    unsigned long long r;
    asm("mov.b64 %0, {%1, %2};" : "=l"(r) : "f"(lo), "f"(hi));
    return r;
}
__device__ __forceinline__ void fma2(unsigned long long& d, unsigned long long a, unsigned long long b) {
    asm("fma.rn.f32x2 %0, %1, %2, %0;" : "+l"(d) : "l"(a), "l"(b));
}
__device__ __forceinline__ void unpk2(unsigned long long v, float& lo, float& hi) {
    asm("mov.b64 {%0, %1}, %2;" : "=f"(lo), "=f"(hi) : "l"(v));
}

// upper-tri pair index for c<=d
#define PIDX(c, d) ((c) * 8 - (c) * ((c) - 1) / 2 + ((d) - (c)))

// ---------------------------------------------------------------------------
// cov body, templated on pair-parity ROLE so each warp-group keeps only 18
// packed accumulators (36 regs) — halves register pressure vs full 36 pairs.
// ---------------------------------------------------------------------------
template <int ROLE>
__device__ __forceinline__ void cov_body(const float* __restrict__ vr,
                                         const float* __restrict__ vi,
                                         float* __restrict__ out) {
    unsigned long long acc[18];
#pragma unroll
    for (int j = 0; j < 18; j++) acc[j] = 0ULL;

#pragma unroll 2
    for (int t = 0; t < TCHUNK; t++) {
        float yr[8], yv[8];
#pragma unroll
        for (int c = 0; c < 8; c++) {
            yr[c] = vr[(size_t)c * TFv + (size_t)t * Ff];
            yv[c] = vi[(size_t)c * TFv + (size_t)t * Ff];
        }
#pragma unroll
        for (int d = 0; d < 8; d++) {
            unsigned long long bR = pk2(yr[d], yr[d]);
            unsigned long long bI = pk2(yv[d], yv[d]);
#pragma unroll
            for (int c = 0; c <= d; c++) {
                if ((PIDX(c, d) & 1) == ROLE) {
                    unsigned long long a1 = pk2(yr[c], yv[c]);
                    unsigned long long a2 = pk2(yv[c], -yr[c]);
                    fma2(acc[PIDX(c, d) >> 1], a1, bR);
                    fma2(acc[PIDX(c, d) >> 1], a2, bI);
                }
            }
        }
    }

#pragma unroll
    for (int d = 0; d < 8; d++) {
#pragma unroll
        for (int c = 0; c <= d; c++) {
            if ((PIDX(c, d) & 1) == ROLE) {
                float re, im;
                unpk2(acc[PIDX(c, d) >> 1], re, im);
                out[(size_t)(2 * PIDX(c, d)) * Ff]     = re;
                out[(size_t)(2 * PIDX(c, d) + 1) * Ff] = im;
            }
        }
    }
}

// ---------------------------------------------------------------------------
// Kernel 1: partial noise covariance, pair-split across warp-groups.
// Block = 128 threads: warps 0-1 = even pairs, warps 2-3 = odd pairs,
// both covering the same 64 dense (chunk,f) slots (shared loads hit L1).
// Grid: (ceil(GCOV/64), Nn).
// ---------------------------------------------------------------------------
__global__ void __launch_bounds__(128, 6) cov_kernel(const float* __restrict__ noise) {
    int slot = threadIdx.x & 63;
    int role = threadIdx.x >> 6;            // warp-uniform: 0 for warps 0-1, 1 for 2-3
    int g = blockIdx.x * 64 + slot;
    if (g >= GCOV) return;
    int chunk = g / Ff;
    int f = g - chunk * Ff;
    int n = blockIdx.y;

    const float* vr = noise + (size_t)n * 2 * Cc * TFv + (size_t)(chunk * TCHUNK) * Ff + f;
    const float* vi = vr + (size_t)Cc * TFv;
    float* out = g_phi + ((size_t)(chunk * Nn + n) * 72) * Ff + f;

    if (role == 0) cov_body<0>(vr, vi, out);
    else           cov_body<1>(vr, vi, out);
}

// ---------------------------------------------------------------------------
// Kernel 2: fold NCHUNK partials, float4-vectorized.
// ---------------------------------------------------------------------------
__global__ void __launch_bounds__(256) reduce_kernel() {
    const int total4 = (Nn * 72 * Ff) / 4;          // 37008
    int idx = blockIdx.x * 256 + threadIdx.x;
    if (idx >= total4) return;
    const float4* src = (const float4*)g_phi;
    float4 s = src[idx];
#pragma unroll
    for (int ch = 1; ch < NCHUNK; ch++) {
        float4 v = src[(size_t)ch * total4 + idx];
        s.x += v.x; s.y += v.y; s.z += v.z; s.w += v.w;
    }
    ((float4*)g_phired)[idx] = s;
}

// ---------------------------------------------------------------------------
// Kernel 3: warp-cooperative 8x8 complex solve (8 lanes per (n,f) problem).
// ---------------------------------------------------------------------------
struct C2 { float r, i; };
__device__ __forceinline__ C2 cmul(C2 a, C2 b) { return C2{a.r * b.r - a.i * b.i, a.r * b.i + a.i * b.r}; }
__device__ __forceinline__ C2 csub(C2 a, C2 b) { return C2{a.r - b.r, a.i - b.i}; }
__device__ __forceinline__ C2 cinv(C2 a) {
    float s = __frcp_rn(a.r * a.r + a.i * a.i);
    return C2{a.r * s, -a.i * s};
}
__device__ __forceinline__ C2 bcast8(unsigned mask, C2 v, int src) {
    return C2{__shfl_sync(mask, v.r, src, 8), __shfl_sync(mask, v.i, src, 8)};
}

__global__ void __launch_bounds__(256) solve_kernel(const float* __restrict__ sv) {
    int gid = blockIdx.x * 256 + threadIdx.x;
    int r = gid & 7;
    int prob = gid >> 3;
    if (prob >= Nn * Ff) prob = Nn * Ff - 1;   // clamp: dup groups write same values
    int n = prob / Ff;
    int f = prob - n * Ff;
    const unsigned mask = 0xFFFFFFFFu;

    const float invT = 1.0f / (float)Tt;
    const float* src = g_phired + (size_t)n * 72 * Ff + f;

    C2 row[9];
#pragma unroll
    for (int c = 0; c < 8; c++) {
        int a = (r < c) ? r : c;
        int b = (r < c) ? c : r;
        int p = a * 8 - a * (a - 1) / 2 + (b - a);
        float re = src[(size_t)(2 * p) * Ff] * invT;
        float im = src[(size_t)(2 * p + 1) * Ff] * invT;
        if (c < r) im = -im;
        if (c == r) { re += LOADC; im += LOADC; }
        row[c] = C2{re, im};
    }
    const float* dr = sv + ((size_t)n * 2 * Ff + f) * Cc;
    C2 dn = C2{dr[r], dr[(size_t)Ff * Cc + r]};
    row[8] = dn;

#pragma unroll
    for (int k = 0; k < 8; k++) {
        C2 piv = bcast8(mask, row[k], k);
        C2 fac = cmul(row[k], cinv(piv));
#pragma unroll
        for (int col = k + 1; col < 9; col++) {
            C2 pk = bcast8(mask, row[col], k);
            if (r > k) row[col] = csub(row[col], cmul(fac, pk));
        }
    }

    C2 s = row[8];
    C2 myx = C2{0.f, 0.f};
#pragma unroll
    for (int k = 7; k >= 0; k--) {
        C2 sk = bcast8(mask, s, k);
        C2 dk = bcast8(mask, row[k], k);
        C2 xk = cmul(sk, cinv(dk));
        if (r == k) myx = xk;
        if (r < k) s = csub(s, cmul(row[k], xk));
    }

    C2 term = C2{dn.r * myx.r + dn.i * myx.i, dn.r * myx.i - dn.i * myx.r};
#pragma unroll
    for (int off = 4; off; off >>= 1) {
        term.r += __shfl_xor_sync(mask, term.r, off, 8);
        term.i += __shfl_xor_sync(mask, term.i, off, 8);
    }
    C2 w = cmul(myx, cinv(term));

    float* wout = g_w16 + ((size_t)n * Ff + f) * 16;
    wout[2 * r]     = w.r;
    wout[2 * r + 1] = -w.i;
}

// ---------------------------------------------------------------------------
// Kernel 4: beamform — two elements per thread sharing f (t and t+300).
// ---------------------------------------------------------------------------
__global__ void __launch_bounds__(256) bf_kernel(const float* __restrict__ mix,
                                                 float* __restrict__ out) {
    int p = blockIdx.x * 256 + threadIdx.x;
    if (p >= HTF) return;
    int n = blockIdx.y;
    int f = p % Ff;

    const float4* wrow = (const float4*)(g_w16 + ((size_t)n * Ff + f) * 16);
    float4 w0 = wrow[0], w1 = wrow[1], w2 = wrow[2], w3 = wrow[3];
    float wr[8] = {w0.x, w0.z, w1.x, w1.z, w2.x, w2.z, w3.x, w3.z};
    float wi[8] = {w0.y, w0.w, w1.y, w1.w, w2.y, w2.w, w3.y, w3.w};

    const float* mbase = mix + (size_t)n * 2 * Cc * TFv;
    float* obase = out + (size_t)n * 2 * TFv;

#pragma unroll
    for (int e = 0; e < 2; e++) {
        int pe = p + e * HTF;
        const float* base = mbase + pe;
        float Xr = 0.f, Xi = 0.f;
#pragma unroll
        for (int c = 0; c < 8; c++) {
            float yr = base[(size_t)c * TFv];
            float yv = base[(size_t)(Cc + c) * TFv];
            Xr += wr[c] * yr - wi[c] * yv;
            Xi += wr[c] * yv + wi[c] * yr;
        }
        obase[pe]       = Xr;
        obase[pe + TFv] = Xi;
    }
}

// ---------------------------------------------------------------------------
extern "C" void kernel_launch(void* const* d_in, const int* in_sizes, int n_in,
                              void* d_out, int out_size) {
    const float* mixture = (const float*)d_in[0];
    const float* noise   = (const float*)d_in[1];
    const float* sv      = (const float*)d_in[2];
    float* out = (float*)d_out;

    // 1. partial covariance (pair-split warp groups)
    dim3 g1((GCOV + 63) / 64, Nn);
    cov_kernel<<<g1, 128>>>(noise);

    // 2. reduce chunk partials (float4)
    int rtotal4 = (Nn * 72 * Ff) / 4;
    reduce_kernel<<<(rtotal4 + 255) / 256, 256>>>();

    // 3. warp-cooperative solve: 8 lanes per (n,f)
    int sthreads = Nn * Ff * 8;
    solve_kernel<<<(sthreads + 255) / 256, 256>>>(sv);

    // 4. beamform: two elements per thread (shared weights), grid.y = n
    dim3 g4((HTF + 255) / 256, Nn);
    bf_kernel<<<g4, 256>>>(mixture, out);
}

// round 17
// speedup vs baseline: 1.0054x; 1.0054x over previous
#include <cuda_runtime.h>
#include <math.h>

// Problem constants
#define Nn 8
#define Cc 8
#define Tt 600
#define Ff 257
#define NCHUNK 30
#define TCHUNK 20               // Tt / NCHUNK
#define LOADC 7.0710678118654754e-04f   // 0.001/sqrt(2)
#define TFv (Tt * Ff)           // 154200
#define HTF (TFv / 2)           // 77100  (t and t+300 share f)
#define GCOV (NCHUNK * Ff)      // 7710 dense (chunk,f) work items per n

// Scratch (device globals — no allocation allowed)
__device__ __align__(16) float g_phi[(size_t)NCHUNK * Nn * 72 * Ff];
__device__ __align__(16) float g_phired[(size_t)Nn * 72 * Ff];
__device__ __align__(16) float g_w16[(size_t)Nn * Ff * 16];   // [n][f][2c(+1)] interleaved conj(w)

// ---- packed f32x2 helpers (Blackwell FFMA2) --------------------------------
__device__ __forceinline__ unsigned long long pk2(float lo, float hi) {
    unsigned long long r;
    asm("mov.b64 %0, {%1, %2};" : "=l"(r) : "f"(lo), "f"(hi));
    return r;
}
__device__ __forceinline__ void fma2(unsigned long long& d, unsigned long long a, unsigned long long b) {
    asm("fma.rn.f32x2 %0, %1, %2, %0;" : "+l"(d) : "l"(a), "l"(b));
}
__device__ __forceinline__ void unpk2(unsigned long long v, float& lo, float& hi) {
    asm("mov.b64 {%0, %1}, %2;" : "=f"(lo), "=f"(hi) : "l"(v));
}

// upper-tri pair index for c<=d
#define PIDX(c, d) ((c) * 8 - (c) * ((c) - 1) / 2 + ((d) - (c)))

// ---------------------------------------------------------------------------
// cov body, templated on pair-parity ROLE so each warp-group keeps only 18
// packed accumulators (36 regs) — halves register pressure vs full 36 pairs.
// ---------------------------------------------------------------------------
template <int ROLE>
__device__ __forceinline__ void cov_body(const float* __restrict__ vr,
                                         const float* __restrict__ vi,
                                         float* __restrict__ out) {
    unsigned long long acc[18];
#pragma unroll
    for (int j = 0; j < 18; j++) acc[j] = 0ULL;

#pragma unroll 2
    for (int t = 0; t < TCHUNK; t++) {
        float yr[8], yv[8];
#pragma unroll
        for (int c = 0; c < 8; c++) {
            yr[c] = vr[(size_t)c * TFv + (size_t)t * Ff];
            yv[c] = vi[(size_t)c * TFv + (size_t)t * Ff];
        }
#pragma unroll
        for (int d = 0; d < 8; d++) {
            unsigned long long bR = pk2(yr[d], yr[d]);
            unsigned long long bI = pk2(yv[d], yv[d]);
#pragma unroll
            for (int c = 0; c <= d; c++) {
                if ((PIDX(c, d) & 1) == ROLE) {
                    unsigned long long a1 = pk2(yr[c], yv[c]);
                    unsigned long long a2 = pk2(yv[c], -yr[c]);
                    fma2(acc[PIDX(c, d) >> 1], a1, bR);
                    fma2(acc[PIDX(c, d) >> 1], a2, bI);
                }
            }
        }
    }

#pragma unroll
    for (int d = 0; d < 8; d++) {
#pragma unroll
        for (int c = 0; c <= d; c++) {
            if ((PIDX(c, d) & 1) == ROLE) {
                float re, im;
                unpk2(acc[PIDX(c, d) >> 1], re, im);
                out[(size_t)(2 * PIDX(c, d)) * Ff]     = re;
                out[(size_t)(2 * PIDX(c, d) + 1) * Ff] = im;
            }
        }
    }
}

// ---------------------------------------------------------------------------
// Kernel 1: partial noise covariance, pair-split across warp-groups.
// Block = 128 threads: warps 0-1 = even pairs, warps 2-3 = odd pairs,
// both covering the same 64 dense (chunk,f) slots (shared loads hit L1).
// Grid: (ceil(GCOV/64), Nn).
// ---------------------------------------------------------------------------
__global__ void __launch_bounds__(128, 6) cov_kernel(const float* __restrict__ noise) {
    int slot = threadIdx.x & 63;
    int role = threadIdx.x >> 6;            // warp-uniform: 0 for warps 0-1, 1 for 2-3
    int g = blockIdx.x * 64 + slot;
    if (g >= GCOV) return;
    int chunk = g / Ff;
    int f = g - chunk * Ff;
    int n = blockIdx.y;

    const float* vr = noise + (size_t)n * 2 * Cc * TFv + (size_t)(chunk * TCHUNK) * Ff + f;
    const float* vi = vr + (size_t)Cc * TFv;
    float* out = g_phi + ((size_t)(chunk * Nn + n) * 72) * Ff + f;

    if (role == 0) cov_body<0>(vr, vi, out);
    else           cov_body<1>(vr, vi, out);
}

// ---------------------------------------------------------------------------
// Kernel 2: fold NCHUNK partials, float4-vectorized.
// ---------------------------------------------------------------------------
__global__ void __launch_bounds__(256) reduce_kernel() {
    const int total4 = (Nn * 72 * Ff) / 4;          // 37008
    int idx = blockIdx.x * 256 + threadIdx.x;
    if (idx >= total4) return;
    const float4* src = (const float4*)g_phi;
    float4 s = src[idx];
#pragma unroll
    for (int ch = 1; ch < NCHUNK; ch++) {
        float4 v = src[(size_t)ch * total4 + idx];
        s.x += v.x; s.y += v.y; s.z += v.z; s.w += v.w;
    }
    ((float4*)g_phired)[idx] = s;
}

// ---------------------------------------------------------------------------
// Kernel 3: warp-cooperative 8x8 complex solve (8 lanes per (n,f) problem).
// ---------------------------------------------------------------------------
struct C2 { float r, i; };
__device__ __forceinline__ C2 cmul(C2 a, C2 b) { return C2{a.r * b.r - a.i * b.i, a.r * b.i + a.i * b.r}; }
__device__ __forceinline__ C2 csub(C2 a, C2 b) { return C2{a.r - b.r, a.i - b.i}; }
__device__ __forceinline__ C2 cinv(C2 a) {
    float s = __frcp_rn(a.r * a.r + a.i * a.i);
    return C2{a.r * s, -a.i * s};
}
__device__ __forceinline__ C2 bcast8(unsigned mask, C2 v, int src) {
    return C2{__shfl_sync(mask, v.r, src, 8), __shfl_sync(mask, v.i, src, 8)};
}

__global__ void __launch_bounds__(256) solve_kernel(const float* __restrict__ sv) {
    int gid = blockIdx.x * 256 + threadIdx.x;
    int r = gid & 7;
    int prob = gid >> 3;
    if (prob >= Nn * Ff) prob = Nn * Ff - 1;   // clamp: dup groups write same values
    int n = prob / Ff;
    int f = prob - n * Ff;
    const unsigned mask = 0xFFFFFFFFu;

    const float invT = 1.0f / (float)Tt;
    const float* src = g_phired + (size_t)n * 72 * Ff + f;

    C2 row[9];
#pragma unroll
    for (int c = 0; c < 8; c++) {
        int a = (r < c) ? r : c;
        int b = (r < c) ? c : r;
        int p = a * 8 - a * (a - 1) / 2 + (b - a);
        float re = src[(size_t)(2 * p) * Ff] * invT;
        float im = src[(size_t)(2 * p + 1) * Ff] * invT;
        if (c < r) im = -im;
        if (c == r) { re += LOADC; im += LOADC; }
        row[c] = C2{re, im};
    }
    const float* dr = sv + ((size_t)n * 2 * Ff + f) * Cc;
    C2 dn = C2{dr[r], dr[(size_t)Ff * Cc + r]};
    row[8] = dn;

#pragma unroll
    for (int k = 0; k < 8; k++) {
        C2 piv = bcast8(mask, row[k], k);
        C2 fac = cmul(row[k], cinv(piv));
#pragma unroll
        for (int col = k + 1; col < 9; col++) {
            C2 pk = bcast8(mask, row[col], k);
            if (r > k) row[col] = csub(row[col], cmul(fac, pk));
        }
    }

    C2 s = row[8];
    C2 myx = C2{0.f, 0.f};
#pragma unroll
    for (int k = 7; k >= 0; k--) {
        C2 sk = bcast8(mask, s, k);
        C2 dk = bcast8(mask, row[k], k);
        C2 xk = cmul(sk, cinv(dk));
        if (r == k) myx = xk;
        if (r < k) s = csub(s, cmul(row[k], xk));
    }

    C2 term = C2{dn.r * myx.r + dn.i * myx.i, dn.r * myx.i - dn.i * myx.r};
#pragma unroll
    for (int off = 4; off; off >>= 1) {
        term.r += __shfl_xor_sync(mask, term.r, off, 8);
        term.i += __shfl_xor_sync(mask, term.i, off, 8);
    }
    C2 w = cmul(myx, cinv(term));

    float* wout = g_w16 + ((size_t)n * Ff + f) * 16;
    wout[2 * r]     = w.r;
    wout[2 * r + 1] = -w.i;
}

// ---------------------------------------------------------------------------
// Kernel 4: beamform — two elements per thread sharing f (t and t+300).
// ---------------------------------------------------------------------------
__global__ void __launch_bounds__(256) bf_kernel(const float* __restrict__ mix,
                                                 float* __restrict__ out) {
    int p = blockIdx.x * 256 + threadIdx.x;
    if (p >= HTF) return;
    int n = blockIdx.y;
    int f = p % Ff;

    const float4* wrow = (const float4*)(g_w16 + ((size_t)n * Ff + f) * 16);
    float4 w0 = wrow[0], w1 = wrow[1], w2 = wrow[2], w3 = wrow[3];
    float wr[8] = {w0.x, w0.z, w1.x, w1.z, w2.x, w2.z, w3.x, w3.z};
    float wi[8] = {w0.y, w0.w, w1.y, w1.w, w2.y, w2.w, w3.y, w3.w};

    const float* mbase = mix + (size_t)n * 2 * Cc * TFv;
    float* obase = out + (size_t)n * 2 * TFv;

#pragma unroll
    for (int e = 0; e < 2; e++) {
        int pe = p + e * HTF;
        const float* base = mbase + pe;
        float Xr = 0.f, Xi = 0.f;
#pragma unroll
        for (int c = 0; c < 8; c++) {
            float yr = base[(size_t)c * TFv];
            float yv = base[(size_t)(Cc + c) * TFv];
            Xr += wr[c] * yr - wi[c] * yv;
            Xi += wr[c] * yv + wi[c] * yr;
        }
        obase[pe]       = Xr;
        obase[pe + TFv] = Xi;
    }
}

// ---------------------------------------------------------------------------
extern "C" void kernel_launch(void* const* d_in, const int* in_sizes, int n_in,
                              void* d_out, int out_size) {
    const float* mixture = (const float*)d_in[0];
    const float* noise   = (const float*)d_in[1];
    const float* sv      = (const float*)d_in[2];
    float* out = (float*)d_out;

    // 1. partial covariance (pair-split warp groups)
    dim3 g1((GCOV + 63) / 64, Nn);
    cov_kernel<<<g1, 128>>>(noise);

    // 2. reduce chunk partials (float4)
    int rtotal4 = (Nn * 72 * Ff) / 4;
    reduce_kernel<<<(rtotal4 + 255) / 256, 256>>>();

    // 3. warp-cooperative solve: 8 lanes per (n,f)
    int sthreads = Nn * Ff * 8;
    solve_kernel<<<(sthreads + 255) / 256, 256>>>(sv);

    // 4. beamform: two elements per thread (shared weights), grid.y = n
    dim3 g4((HTF + 255) / 256, Nn);
    bf_kernel<<<g4, 256>>>(mixture, out);
}